// round 7
// baseline (speedup 1.0000x reference)
#include <cuda_runtime.h>
#include <cstdint>
#include <math.h>

// LSTMCell fused via mma.sync tf32 (m16n8k8) GEMMs — compute_103-safe PTX.
//   gates = g_xh  @ Wt1^T + bias             (K=1024, N=2048)
//   s     = sigmoid(g_xme @ Wt2^T + mb)*me   (K=2048, N=1536)
//   t     = g_s @ Wt3^T ; LSTM epilogue      (K=1536, N=512)
// All operands pre-rounded to tf32 (rna). 3-stage all-cp.async pipeline,
// ONE __syncthreads per BK=32 stage. ldmatrix.x4 fragment loads.

#define BATCH 16384

// ---------------- scratch (__device__ globals: no allocations allowed) ----
__device__ float g_gates[(size_t)BATCH * 2048];        // 128 MiB
__device__ float g_s[(size_t)BATCH * 1536];            //  96 MiB
__device__ float g_xh[(size_t)BATCH * 1024];           //  64 MiB  [rna(x)|rna(h)]
__device__ float g_xme[(size_t)BATCH * 2048];          // 128 MiB  [rna(x)|rna(me)]
__device__ float g_Wt1[(size_t)2048 * 1024];           // [n][k] K-major
__device__ float g_Wt2[(size_t)1536 * 2048];
__device__ float g_Wt3[(size_t)512 * 1536];

__device__ __forceinline__ float rna_tf32(float x) {
    float r; asm("cvt.rna.tf32.f32 %0, %1;" : "=f"(r) : "f"(x)); return r;
}
__device__ __forceinline__ float sigf(float x) { return 1.0f / (1.0f + __expf(-x)); }
__device__ __forceinline__ float tanh_(float x) { return 2.0f * sigf(2.0f * x) - 1.0f; }

__device__ __forceinline__ void mma_tf32(float& c0, float& c1, float& c2, float& c3,
                                         uint32_t a0, uint32_t a1, uint32_t a2, uint32_t a3,
                                         uint32_t b0, uint32_t b1) {
    asm volatile(
        "mma.sync.aligned.m16n8k8.row.col.f32.tf32.tf32.f32 "
        "{%0,%1,%2,%3}, {%4,%5,%6,%7}, {%8,%9}, {%0,%1,%2,%3};"
        : "+f"(c0), "+f"(c1), "+f"(c2), "+f"(c3)
        : "r"(a0), "r"(a1), "r"(a2), "r"(a3), "r"(b0), "r"(b1));
}

__device__ __forceinline__ void ldsm_x4(uint32_t& r0, uint32_t& r1,
                                        uint32_t& r2, uint32_t& r3, uint32_t addr) {
    asm volatile("ldmatrix.sync.aligned.m8n8.x4.shared.b16 {%0,%1,%2,%3}, [%4];"
                 : "=r"(r0), "=r"(r1), "=r"(r2), "=r"(r3) : "r"(addr));
}

#define CP_ASYNC16(dst_u32, src_ptr) \
    asm volatile("cp.async.cg.shared.global [%0], [%1], 16;" \
                 :: "r"(dst_u32), "l"(src_ptr))
#define CP_COMMIT() asm volatile("cp.async.commit_group;")
#define CP_WAIT1()  asm volatile("cp.async.wait_group 1;" ::: "memory")
#define CP_WAIT0()  asm volatile("cp.async.wait_group 0;" ::: "memory")

// ---------------- merged weight transpose + tf32 rounding pre-pass --------
__device__ __forceinline__ void tr_body(const float* __restrict__ src,
                                        float* __restrict__ dst,
                                        int C, int dstStride, int bx, int by) {
    __shared__ float t[32][33];
    const int c0 = bx << 5, r0 = by << 5;
    const int tx = threadIdx.x, ty = threadIdx.y;
#pragma unroll
    for (int j = ty; j < 32; j += 8)
        t[j][tx] = rna_tf32(src[(size_t)(r0 + j) * C + c0 + tx]);
    __syncthreads();
#pragma unroll
    for (int j = ty; j < 32; j += 8)
        dst[(size_t)(c0 + j) * dstStride + r0 + tx] = t[tx][j];
}

__global__ void __launch_bounds__(256) transpose_all(
    const float* __restrict__ W_ih,  const float* __restrict__ W_hh,
    const float* __restrict__ W_memi, const float* __restrict__ W_memh,
    const float* __restrict__ W_memt)
{
    int id = blockIdx.x;
    if (id < 1024)      tr_body(W_ih,   g_Wt1,        2048, 1024, id % 64, id / 64);
    else if (id < 2048) { id -= 1024; tr_body(W_hh,   g_Wt1 + 512, 2048, 1024, id % 64, id / 64); }
    else if (id < 2816) { id -= 2048; tr_body(W_memi, g_Wt2,       1536, 2048, id % 48, id / 48); }
    else if (id < 5120) { id -= 2816; tr_body(W_memh, g_Wt2 + 512, 1536, 2048, id % 48, id / 48); }
    else                { id -= 5120; tr_body(W_memt, g_Wt3,        512, 1536, id % 16, id / 16); }
}

// ---------------- activation pack + rna pre-pass --------------------------
// g_xh[r][0:512]=rna(x[r]) [512:1024]=rna(h[r]);
// g_xme[r][0:512]=rna(x[r]) [512:2048]=rna(me[r]).
__global__ void __launch_bounds__(256) pack_rna(
    const float* __restrict__ x, const float* __restrict__ h,
    const float* __restrict__ me)
{
    const int i = blockIdx.x * 256 + threadIdx.x;      // float4 index
    const int XH4 = BATCH * 256;                       // 1024/4 per row
    float4 v;
    if (i < XH4) {
        const int row = i >> 8, c = (i & 255) << 2;
        const float* src = (c < 512) ? x + (size_t)row * 512 + c
                                     : h + (size_t)row * 512 + (c - 512);
        v = *(const float4*)src;
        v.x = rna_tf32(v.x); v.y = rna_tf32(v.y);
        v.z = rna_tf32(v.z); v.w = rna_tf32(v.w);
        *(float4*)(g_xh + (size_t)row * 1024 + c) = v;
    } else {
        const int j = i - XH4;
        const int row = j >> 9, c = (j & 511) << 2;
        const float* src = (c < 512) ? x + (size_t)row * 512 + c
                                     : me + (size_t)row * 1536 + (c - 512);
        v = *(const float4*)src;
        v.x = rna_tf32(v.x); v.y = rna_tf32(v.y);
        v.z = rna_tf32(v.z); v.w = rna_tf32(v.w);
        *(float4*)(g_xme + (size_t)row * 2048 + c) = v;
    }
}

// ---------------- main GEMM ------------------------------------------------
// Tile 128x128, BK=32, 8 warps (2M x 4N), each warp 64x32 = 4x4 m16n8k8.
// 3 SMEM stages, each A[128][36]+B[128][36] floats; one barrier/stage.
#define PAD 36
#define TILE_F (128 * PAD)
#define STAGE_F (2 * TILE_F)
#define SMEM_BYTES (3 * STAGE_F * 4)   // 110592

template <int MODE>
__global__ void __launch_bounds__(256, 2) mma_gemm(
    const float* __restrict__ Ap, int lda, int K,
    const float* __restrict__ Wt,
    const float* __restrict__ bias,
    const float* __restrict__ me,
    const float* __restrict__ cin, const float* __restrict__ hin,
    float* __restrict__ outp)
{
    extern __shared__ float smem[];           // [3 stage][A|B][TILE_F]
    const uint32_t sbase = (uint32_t)__cvta_generic_to_shared(smem);
    const int tid = threadIdx.x, wid = tid >> 5, lane = tid & 31;
    const int bm = blockIdx.y << 7, bn = blockIdx.x << 7;
    const int wm = (wid >> 2) << 6;
    const int wn = (wid & 3) << 5;
    const int grp = lane >> 2, qd = lane & 3;

    float acc[4][4][4];
#pragma unroll
    for (int mt = 0; mt < 4; mt++)
#pragma unroll
        for (int nt = 0; nt < 4; nt++)
#pragma unroll
            for (int q = 0; q < 4; q++) acc[mt][nt][q] = 0.0f;

    const int nst = K >> 5;

    // ldmatrix per-lane addresses (byte offsets within a stage):
    const int l7 = lane & 7;
    const uint32_t a_off =
        (uint32_t)(((wm + l7 + (((lane >> 3) & 1) << 3)) * PAD) << 2) +
        (uint32_t)((((lane >> 4) & 1)) << 4);
    const uint32_t b_off = (uint32_t)(TILE_F << 2) +
        (uint32_t)(((wn + (((lane >> 4) & 1) << 3) + l7) * PAD) << 2) +
        (uint32_t)((((lane >> 3) & 1)) << 4);

    // staging map: i = tid + t*256 -> row = i>>3, q4 = (i&7)*4
#define ISSUE_AB(S, BUF) do {                                                   \
    const int _k0 = (S) << 5;                                                   \
    _Pragma("unroll")                                                           \
    for (int t = 0; t < 4; t++) {                                               \
        const int i = tid + (t << 8);                                           \
        const int row = i >> 3, q4 = (i & 7) << 2;                              \
        const uint32_t dA = sbase +                                             \
            (uint32_t)((((BUF) * STAGE_F) + row * PAD + q4) << 2);              \
        CP_ASYNC16(dA, Ap + (size_t)(bm + row) * lda + _k0 + q4);               \
        const uint32_t dB = sbase +                                             \
            (uint32_t)((((BUF) * STAGE_F) + TILE_F + row * PAD + q4) << 2);     \
        CP_ASYNC16(dB, Wt + (size_t)(bn + row) * K + _k0 + q4);                 \
    }                                                                           \
    CP_COMMIT(); } while (0)

    ISSUE_AB(0, 0);
    ISSUE_AB(1, 1);

    int buf = 0;   // = s % 3
    for (int s = 0; s < nst; s++) {
        if (s + 1 < nst) CP_WAIT1(); else CP_WAIT0();
        __syncthreads();
        if (s + 2 < nst) {
            const int wbuf = (buf + 2 >= 3) ? buf - 1 : buf + 2;
            ISSUE_AB(s + 2, wbuf);
        }

        const uint32_t abuf = sbase + (uint32_t)((buf * STAGE_F) << 2) + a_off;
        const uint32_t bbuf = sbase + (uint32_t)((buf * STAGE_F) << 2) + b_off;
#pragma unroll
        for (int kk = 0; kk < 4; kk++) {
            uint32_t af[4][4];
#pragma unroll
            for (int mt = 0; mt < 4; mt++)
                ldsm_x4(af[mt][0], af[mt][1], af[mt][2], af[mt][3],
                        abuf + (uint32_t)(mt * (16 * PAD * 4)) + (uint32_t)(kk * 32));
            uint32_t bf[4][2];
#pragma unroll
            for (int p2 = 0; p2 < 2; p2++)
                ldsm_x4(bf[2 * p2][0], bf[2 * p2][1], bf[2 * p2 + 1][0], bf[2 * p2 + 1][1],
                        bbuf + (uint32_t)(p2 * (16 * PAD * 4)) + (uint32_t)(kk * 32));
#pragma unroll
            for (int mt = 0; mt < 4; mt++)
#pragma unroll
                for (int nt = 0; nt < 4; nt++)
                    mma_tf32(acc[mt][nt][0], acc[mt][nt][1],
                             acc[mt][nt][2], acc[mt][nt][3],
                             af[mt][0], af[mt][1], af[mt][2], af[mt][3],
                             bf[nt][0], bf[nt][1]);
        }
        buf = (buf + 1 >= 3) ? 0 : buf + 1;
    }

    // ---- fused epilogues (c frag rows grp/grp+8, cols 2qd/2qd+1) ----
#pragma unroll
    for (int mt = 0; mt < 4; mt++) {
#pragma unroll
        for (int nt = 0; nt < 4; nt++) {
#pragma unroll
            for (int hrow = 0; hrow < 2; hrow++) {
                const int r = bm + wm + (mt << 4) + grp + (hrow << 3);
                const int cc = bn + wn + (nt << 3) + (qd << 1);
                const float v0 = acc[mt][nt][hrow * 2];
                const float v1 = acc[mt][nt][hrow * 2 + 1];
                if (MODE == 0) {
                    const float2 b2 = *(const float2*)(bias + cc);
                    float2 o = {v0 + b2.x, v1 + b2.y};
                    *(float2*)(g_gates + (size_t)r * 2048 + cc) = o;
                } else if (MODE == 1) {
                    const float2 b2 = *(const float2*)(bias + cc);
                    const float2 m2 = *(const float2*)(me + (size_t)r * 1536 + cc);
                    // store rna-rounded: g_s is the A operand of GEMM2
                    float2 o = {rna_tf32(sigf(v0 + b2.x) * m2.x),
                                rna_tf32(sigf(v1 + b2.y) * m2.y)};
                    *(float2*)(g_s + (size_t)r * 1536 + cc) = o;
                } else {
                    const size_t gb = (size_t)r * 2048 + cc;
                    const float2 f2 = *(const float2*)(g_gates + gb);
                    const float2 i2 = *(const float2*)(g_gates + gb + 512);
                    const float2 o2 = *(const float2*)(g_gates + gb + 1024);
                    const float2 g2 = *(const float2*)(g_gates + gb + 1536);
                    const float2 c2 = *(const float2*)(cin + (size_t)r * 512 + cc);
                    const float2 h2 = *(const float2*)(hin + (size_t)r * 512 + cc);
                    float2 oh, oc;
                    {
                        float cn = sigf(f2.x) * c2.x + sigf(i2.x) * tanh_(g2.x) + v0;
                        float hn = sigf(o2.x) * tanh_(cn);
                        oh.x = 0.8f * hn + 0.2f * h2.x;
                        oc.x = 0.8f * cn + 0.2f * c2.x;
                    }
                    {
                        float cn = sigf(f2.y) * c2.y + sigf(i2.y) * tanh_(g2.y) + v1;
                        float hn = sigf(o2.y) * tanh_(cn);
                        oh.y = 0.8f * hn + 0.2f * h2.y;
                        oc.y = 0.8f * cn + 0.2f * c2.y;
                    }
                    *(float2*)(outp + (size_t)r * 512 + cc) = oh;
                    *(float2*)(outp + (size_t)BATCH * 512 + (size_t)r * 512 + cc) = oc;
                }
            }
        }
    }
}

// ---------------- host ----------------------------------------------------
extern "C" void kernel_launch(void* const* d_in, const int* in_sizes, int n_in,
                              void* d_out, int out_size)
{
    const float* x      = (const float*)d_in[0];
    const float* h      = (const float*)d_in[1];
    const float* c      = (const float*)d_in[2];
    const float* me     = (const float*)d_in[3];
    const float* W_ih   = (const float*)d_in[4];
    const float* W_hh   = (const float*)d_in[5];
    const float* bias   = (const float*)d_in[6];
    const float* W_memi = (const float*)d_in[7];
    const float* W_memh = (const float*)d_in[8];
    const float* W_memt = (const float*)d_in[9];
    const float* mem_b  = (const float*)d_in[10];
    float* out = (float*)d_out;

    cudaFuncSetAttribute(mma_gemm<0>, cudaFuncAttributeMaxDynamicSharedMemorySize, SMEM_BYTES);
    cudaFuncSetAttribute(mma_gemm<1>, cudaFuncAttributeMaxDynamicSharedMemorySize, SMEM_BYTES);
    cudaFuncSetAttribute(mma_gemm<2>, cudaFuncAttributeMaxDynamicSharedMemorySize, SMEM_BYTES);

    float *wt1, *wt2, *wt3, *xh, *xme, *sp;
    cudaGetSymbolAddress((void**)&wt1, g_Wt1);
    cudaGetSymbolAddress((void**)&wt2, g_Wt2);
    cudaGetSymbolAddress((void**)&wt3, g_Wt3);
    cudaGetSymbolAddress((void**)&xh,  g_xh);
    cudaGetSymbolAddress((void**)&xme, g_xme);
    cudaGetSymbolAddress((void**)&sp,  g_s);

    transpose_all<<<5888, dim3(32, 8)>>>(W_ih, W_hh, W_memi, W_memh, W_memt);
    pack_rna<<<49152, 256>>>(x, h, me);

    mma_gemm<0><<<dim3(16, 128), 256, SMEM_BYTES>>>(
        xh, 1024, 1024, wt1, bias, nullptr, nullptr, nullptr, nullptr);

    mma_gemm<1><<<dim3(12, 128), 256, SMEM_BYTES>>>(
        xme, 2048, 2048, wt2, mem_b, me, nullptr, nullptr, nullptr);

    mma_gemm<2><<<dim3(4, 128), 256, SMEM_BYTES>>>(
        sp, 1536, 1536, wt3, nullptr, nullptr, c, h, out);
}

// round 8
// speedup vs baseline: 1.6911x; 1.6911x over previous
#include <cuda_runtime.h>
#include <cuda_fp16.h>
#include <cstdint>
#include <math.h>

// LSTMCell fused via mma.sync fp16 (m16n8k16, f32 accum) GEMMs.
//   gates = [x|h] @ Wt1^T + bias             (K=1024, N=2048)
//   s     = sigmoid([x|me] @ Wt2^T + mb)*me  (K=2048, N=1536)
//   t     = s @ Wt3^T ; LSTM epilogue        (K=1536, N=512)
// fp16 operands (same 10-bit mantissa as tf32), fp32 accumulate.
// 3-stage all-cp.async pipeline, BK=64, one __syncthreads per stage.

#define BATCH 16384

// ---------------- scratch (__device__ globals: no allocations allowed) ----
__device__ float  g_gates[(size_t)BATCH * 2048];   // 128 MiB fp32
__device__ __half g_x16[(size_t)BATCH * 512];      // 16 MiB
__device__ __half g_h16[(size_t)BATCH * 512];      // 16 MiB
__device__ __half g_me16[(size_t)BATCH * 1536];    // 48 MiB
__device__ __half g_s16[(size_t)BATCH * 1536];     // 48 MiB
__device__ __half g_Wt1[(size_t)2048 * 1024];      // [n][k] K-major fp16
__device__ __half g_Wt2[(size_t)1536 * 2048];
__device__ __half g_Wt3[(size_t)512 * 1536];

__device__ __forceinline__ float sigf(float x) { return 1.0f / (1.0f + __expf(-x)); }
__device__ __forceinline__ float tanh_(float x) { return 2.0f * sigf(2.0f * x) - 1.0f; }

__device__ __forceinline__ void mma_f16(float& c0, float& c1, float& c2, float& c3,
                                        uint32_t a0, uint32_t a1, uint32_t a2, uint32_t a3,
                                        uint32_t b0, uint32_t b1) {
    asm volatile(
        "mma.sync.aligned.m16n8k16.row.col.f32.f16.f16.f32 "
        "{%0,%1,%2,%3}, {%4,%5,%6,%7}, {%8,%9}, {%0,%1,%2,%3};"
        : "+f"(c0), "+f"(c1), "+f"(c2), "+f"(c3)
        : "r"(a0), "r"(a1), "r"(a2), "r"(a3), "r"(b0), "r"(b1));
}

__device__ __forceinline__ void ldsm_x4(uint32_t& r0, uint32_t& r1,
                                        uint32_t& r2, uint32_t& r3, uint32_t addr) {
    asm volatile("ldmatrix.sync.aligned.m8n8.x4.shared.b16 {%0,%1,%2,%3}, [%4];"
                 : "=r"(r0), "=r"(r1), "=r"(r2), "=r"(r3) : "r"(addr));
}

#define CP_ASYNC16(dst_u32, src_ptr) \
    asm volatile("cp.async.cg.shared.global [%0], [%1], 16;" \
                 :: "r"(dst_u32), "l"(src_ptr))
#define CP_COMMIT() asm volatile("cp.async.commit_group;")
#define CP_WAIT1()  asm volatile("cp.async.wait_group 1;" ::: "memory")
#define CP_WAIT0()  asm volatile("cp.async.wait_group 0;" ::: "memory")

// ---------------- weight transpose -> fp16 K-major pre-pass ---------------
__device__ __forceinline__ void tr_body(const float* __restrict__ src,
                                        __half* __restrict__ dst,
                                        int C, int dstStride, int bx, int by) {
    __shared__ float t[32][33];
    const int c0 = bx << 5, r0 = by << 5;
    const int tx = threadIdx.x, ty = threadIdx.y;
#pragma unroll
    for (int j = ty; j < 32; j += 8)
        t[j][tx] = src[(size_t)(r0 + j) * C + c0 + tx];
    __syncthreads();
#pragma unroll
    for (int j = ty; j < 32; j += 8)
        dst[(size_t)(c0 + j) * dstStride + r0 + tx] = __float2half_rn(t[tx][j]);
}

__global__ void __launch_bounds__(256) transpose_all(
    const float* __restrict__ W_ih,  const float* __restrict__ W_hh,
    const float* __restrict__ W_memi, const float* __restrict__ W_memh,
    const float* __restrict__ W_memt)
{
    int id = blockIdx.x;
    if (id < 1024)      tr_body(W_ih,   g_Wt1,        2048, 1024, id % 64, id / 64);
    else if (id < 2048) { id -= 1024; tr_body(W_hh,   g_Wt1 + 512, 2048, 1024, id % 64, id / 64); }
    else if (id < 2816) { id -= 2048; tr_body(W_memi, g_Wt2,       1536, 2048, id % 48, id / 48); }
    else if (id < 5120) { id -= 2816; tr_body(W_memh, g_Wt2 + 512, 1536, 2048, id % 48, id / 48); }
    else                { id -= 5120; tr_body(W_memt, g_Wt3,        512, 1536, id % 16, id / 16); }
}

// ---------------- activation fp16 conversion pre-pass ---------------------
__global__ void __launch_bounds__(256) pack_half(
    const float* __restrict__ x, const float* __restrict__ h,
    const float* __restrict__ me)
{
    const int i = blockIdx.x * 256 + threadIdx.x;   // float4 index
    const int N1 = BATCH * 128;                     // x
    const int N2 = N1 + BATCH * 128;                // h
    const float* src; __half* dst;
    size_t off;
    if (i < N1)      { off = (size_t)i << 2;        src = x;  dst = g_x16; }
    else if (i < N2) { off = (size_t)(i - N1) << 2; src = h;  dst = g_h16; }
    else             { off = (size_t)(i - N2) << 2; src = me; dst = g_me16; }
    const float4 v = *(const float4*)(src + off);
    const __half2 lo = __floats2half2_rn(v.x, v.y);
    const __half2 hi = __floats2half2_rn(v.z, v.w);
    uint2 u;
    u.x = *(const uint32_t*)&lo;
    u.y = *(const uint32_t*)&hi;
    *(uint2*)(dst + off) = u;
}

// ---------------- main GEMM ------------------------------------------------
// Tile 128x128, BK=64, 8 warps (2M x 4N), warp 64x32 = 4x4 m16n8k16 per kk.
// SMEM per stage: A[128][72] + B[128][72] halves (row 144B: conflict-free
// ldmatrix since 144*{0..7} mod 128 are distinct 16B slots). 3 stages.
#define PADH 72
#define ROWB 144                    // bytes per SMEM row
#define TILE_B (128 * ROWB)         // 18432 bytes per operand
#define STAGE_B (2 * TILE_B)        // 36864
#define SMEM_BYTES (3 * STAGE_B)    // 110592

template <int MODE>
__global__ void __launch_bounds__(256, 2) mma_gemm(
    const __half* __restrict__ A0, int lda0,
    const __half* __restrict__ A1, int lda1,
    int K0, int K,
    const __half* __restrict__ Wt,
    const float* __restrict__ bias,
    const float* __restrict__ me,
    const float* __restrict__ cin, const float* __restrict__ hin,
    float* __restrict__ outp)
{
    extern __shared__ char smem[];
    const uint32_t sbase = (uint32_t)__cvta_generic_to_shared(smem);
    const int tid = threadIdx.x, wid = tid >> 5, lane = tid & 31;
    const int bm = blockIdx.y << 7, bn = blockIdx.x << 7;
    const int wm = (wid >> 2) << 6;
    const int wn = (wid & 3) << 5;
    const int grp = lane >> 2, qd = lane & 3;

    float acc[4][4][4];
#pragma unroll
    for (int mt = 0; mt < 4; mt++)
#pragma unroll
        for (int nt = 0; nt < 4; nt++)
#pragma unroll
            for (int q = 0; q < 4; q++) acc[mt][nt][q] = 0.0f;

    const int nst = K >> 6;

    // ldmatrix per-lane byte offsets within a stage (kk adds 32B):
    const int l7 = lane & 7;
    const uint32_t a_off =
        (uint32_t)((wm + l7 + (((lane >> 3) & 1) << 3)) * ROWB) +
        (uint32_t)((((lane >> 4) & 1)) << 4);
    const uint32_t b_off = (uint32_t)TILE_B +
        (uint32_t)((wn + (((lane >> 4) & 1) << 3) + l7) * ROWB) +
        (uint32_t)((((lane >> 3) & 1)) << 4);

    // cp.async staging: 2048 16B chunks/stage; thread does 4 A + 4 B.
    // chunk i (0..1023): row = i>>3, c16 = i&7 (8 halves each)
#define ISSUE_AB(S, BUF) do {                                                   \
    const int _k0 = (S) << 6;                                                   \
    _Pragma("unroll")                                                           \
    for (int t = 0; t < 4; t++) {                                               \
        const int i = tid + (t << 8);                                           \
        const int row = i >> 3, c16 = i & 7;                                    \
        const int ka = _k0 + (c16 << 3);                                        \
        const __half* pa = (ka < K0)                                            \
            ? A0 + (size_t)(bm + row) * lda0 + ka                               \
            : A1 + (size_t)(bm + row) * lda1 + (ka - K0);                       \
        const uint32_t dA = sbase +                                             \
            (uint32_t)((BUF) * STAGE_B + row * ROWB + (c16 << 4));              \
        CP_ASYNC16(dA, pa);                                                     \
        const uint32_t dB = sbase +                                             \
            (uint32_t)((BUF) * STAGE_B + TILE_B + row * ROWB + (c16 << 4));     \
        CP_ASYNC16(dB, Wt + (size_t)(bn + row) * K + ka);                       \
    }                                                                           \
    CP_COMMIT(); } while (0)

    ISSUE_AB(0, 0);
    ISSUE_AB(1, 1);

    int buf = 0;   // = s % 3
    for (int s = 0; s < nst; s++) {
        if (s + 1 < nst) CP_WAIT1(); else CP_WAIT0();
        __syncthreads();
        if (s + 2 < nst) {
            const int wbuf = (buf + 2 >= 3) ? buf - 1 : buf + 2;
            ISSUE_AB(s + 2, wbuf);
        }

        const uint32_t abuf = sbase + (uint32_t)(buf * STAGE_B) + a_off;
        const uint32_t bbuf = sbase + (uint32_t)(buf * STAGE_B) + b_off;
#pragma unroll
        for (int kk = 0; kk < 4; kk++) {              // 4 x k16 per BK=64
            uint32_t af[4][4];
#pragma unroll
            for (int mt = 0; mt < 4; mt++)
                ldsm_x4(af[mt][0], af[mt][1], af[mt][2], af[mt][3],
                        abuf + (uint32_t)(mt * (16 * ROWB)) + (uint32_t)(kk * 32));
            uint32_t bf[4][2];
#pragma unroll
            for (int p2 = 0; p2 < 2; p2++)
                ldsm_x4(bf[2 * p2][0], bf[2 * p2][1], bf[2 * p2 + 1][0], bf[2 * p2 + 1][1],
                        bbuf + (uint32_t)(p2 * (16 * ROWB)) + (uint32_t)(kk * 32));
#pragma unroll
            for (int mt = 0; mt < 4; mt++)
#pragma unroll
                for (int nt = 0; nt < 4; nt++)
                    mma_f16(acc[mt][nt][0], acc[mt][nt][1],
                            acc[mt][nt][2], acc[mt][nt][3],
                            af[mt][0], af[mt][1], af[mt][2], af[mt][3],
                            bf[nt][0], bf[nt][1]);
        }
        buf = (buf + 1 >= 3) ? 0 : buf + 1;
    }

    // ---- fused epilogues (c frag rows grp/grp+8, cols 2qd/2qd+1) ----
#pragma unroll
    for (int mt = 0; mt < 4; mt++) {
#pragma unroll
        for (int nt = 0; nt < 4; nt++) {
#pragma unroll
            for (int hrow = 0; hrow < 2; hrow++) {
                const int r = bm + wm + (mt << 4) + grp + (hrow << 3);
                const int cc = bn + wn + (nt << 3) + (qd << 1);
                const float v0 = acc[mt][nt][hrow * 2];
                const float v1 = acc[mt][nt][hrow * 2 + 1];
                if (MODE == 0) {
                    const float2 b2 = *(const float2*)(bias + cc);
                    float2 o = {v0 + b2.x, v1 + b2.y};
                    *(float2*)(g_gates + (size_t)r * 2048 + cc) = o;
                } else if (MODE == 1) {
                    const float2 b2 = *(const float2*)(bias + cc);
                    const float2 m2 = *(const float2*)(me + (size_t)r * 1536 + cc);
                    const __half2 o = __floats2half2_rn(sigf(v0 + b2.x) * m2.x,
                                                        sigf(v1 + b2.y) * m2.y);
                    *(__half2*)(g_s16 + (size_t)r * 1536 + cc) = o;
                } else {
                    const size_t gb = (size_t)r * 2048 + cc;
                    const float2 f2 = *(const float2*)(g_gates + gb);
                    const float2 i2 = *(const float2*)(g_gates + gb + 512);
                    const float2 o2 = *(const float2*)(g_gates + gb + 1024);
                    const float2 g2 = *(const float2*)(g_gates + gb + 1536);
                    const float2 c2 = *(const float2*)(cin + (size_t)r * 512 + cc);
                    const float2 h2 = *(const float2*)(hin + (size_t)r * 512 + cc);
                    float2 oh, oc;
                    {
                        float cn = sigf(f2.x) * c2.x + sigf(i2.x) * tanh_(g2.x) + v0;
                        float hn = sigf(o2.x) * tanh_(cn);
                        oh.x = 0.8f * hn + 0.2f * h2.x;
                        oc.x = 0.8f * cn + 0.2f * c2.x;
                    }
                    {
                        float cn = sigf(f2.y) * c2.y + sigf(i2.y) * tanh_(g2.y) + v1;
                        float hn = sigf(o2.y) * tanh_(cn);
                        oh.y = 0.8f * hn + 0.2f * h2.y;
                        oc.y = 0.8f * cn + 0.2f * c2.y;
                    }
                    *(float2*)(outp + (size_t)r * 512 + cc) = oh;
                    *(float2*)(outp + (size_t)BATCH * 512 + (size_t)r * 512 + cc) = oc;
                }
            }
        }
    }
}

// ---------------- host ----------------------------------------------------
extern "C" void kernel_launch(void* const* d_in, const int* in_sizes, int n_in,
                              void* d_out, int out_size)
{
    const float* x      = (const float*)d_in[0];
    const float* h      = (const float*)d_in[1];
    const float* c      = (const float*)d_in[2];
    const float* me     = (const float*)d_in[3];
    const float* W_ih   = (const float*)d_in[4];
    const float* W_hh   = (const float*)d_in[5];
    const float* bias   = (const float*)d_in[6];
    const float* W_memi = (const float*)d_in[7];
    const float* W_memh = (const float*)d_in[8];
    const float* W_memt = (const float*)d_in[9];
    const float* mem_b  = (const float*)d_in[10];
    float* out = (float*)d_out;

    cudaFuncSetAttribute(mma_gemm<0>, cudaFuncAttributeMaxDynamicSharedMemorySize, SMEM_BYTES);
    cudaFuncSetAttribute(mma_gemm<1>, cudaFuncAttributeMaxDynamicSharedMemorySize, SMEM_BYTES);
    cudaFuncSetAttribute(mma_gemm<2>, cudaFuncAttributeMaxDynamicSharedMemorySize, SMEM_BYTES);

    __half *wt1, *wt2, *wt3, *x16, *h16, *me16, *s16;
    cudaGetSymbolAddress((void**)&wt1, g_Wt1);
    cudaGetSymbolAddress((void**)&wt2, g_Wt2);
    cudaGetSymbolAddress((void**)&wt3, g_Wt3);
    cudaGetSymbolAddress((void**)&x16, g_x16);
    cudaGetSymbolAddress((void**)&h16, g_h16);
    cudaGetSymbolAddress((void**)&me16, g_me16);
    cudaGetSymbolAddress((void**)&s16, g_s16);

    transpose_all<<<5888, dim3(32, 8)>>>(W_ih, W_hh, W_memi, W_memh, W_memt);
    pack_half<<<(BATCH * 640) / 256, 256>>>(x, h, me);

    // gates = [x|h] @ Wt1^T + bias
    mma_gemm<0><<<dim3(16, 128), 256, SMEM_BYTES>>>(
        x16, 512, h16, 512, 512, 1024, wt1, bias, nullptr, nullptr, nullptr, nullptr);

    // s = sigmoid([x|me] @ Wt2^T + mem_bias) * me   (stored fp16)
    mma_gemm<1><<<dim3(12, 128), 256, SMEM_BYTES>>>(
        x16, 512, me16, 1536, 512, 2048, wt2, mem_b, me, nullptr, nullptr, nullptr);

    // t = s @ Wt3^T ; LSTM epilogue -> out
    mma_gemm<2><<<dim3(4, 128), 256, SMEM_BYTES>>>(
        s16, 1536, s16, 1536, 1536, 1536, wt3, nullptr, nullptr, c, h, out);
}